// round 8
// baseline (speedup 1.0000x reference)
#include <cuda_runtime.h>
#include <cuda_fp16.h>
#include <math.h>

#define BIGF 1000000000.0f
#define SIG 2112

// Cost matrix, fp16, SKEWED layout for the 8-rows-per-thread DTW:
// slot(b, sigma, r) at halves-address ((b*SIG + sigma)*1024 + r) holds
// C[r][kc] with kc = sigma - ((r>>3)&31). Zero-initialized; slots with kc
// outside [0,2046] are never written and stay 0.0h (dtw relies on this).
static __device__ __align__(256) __half g_CH[69206016];   // 32*2112*1024
static __device__ float g_n1[32 * 1024];
static __device__ float g_n2[32 * 1024];

// ---------------------------------------------------------------------------
// Kernel 0: row squared norms (fp32). One warp per row.
// ---------------------------------------------------------------------------
__global__ __launch_bounds__(256) void norms_kernel(const float* __restrict__ s1,
                                                    const float* __restrict__ s2) {
    int b = blockIdx.y;
    const float* s = blockIdx.z ? s2 : s1;
    float* o = blockIdx.z ? g_n2 : g_n1;
    int lane = threadIdx.x & 31;
    int wid = threadIdx.x >> 5;
    int r = blockIdx.x * 8 + wid;
    const float4* p = (const float4*)(s + ((size_t)b * 1024 + r) * 128);
    float4 v = p[lane];
    float acc = v.x * v.x + v.y * v.y + v.z * v.z + v.w * v.w;
#pragma unroll
    for (int off = 16; off; off >>= 1)
        acc += __shfl_xor_sync(0xffffffffu, acc, off);
    if (lane == 0) o[b * 1024 + r] = acc;
}

// ---------------------------------------------------------------------------
// Kernel 1: cost matrix via tf32 mma.sync.m16n8k8 (unchanged math from R6/R7).
// Writeout uses the new sigma layout: sigma = kc + ((r>>3)&31).
// ---------------------------------------------------------------------------
#define MMA_TF32(C0, C1, C2, C3, A0, A1, A2, A3, B0, B1)                      \
    asm volatile(                                                              \
        "mma.sync.aligned.m16n8k8.row.col.f32.tf32.tf32.f32 "                  \
        "{%0,%1,%2,%3}, {%4,%5,%6,%7}, {%8,%9}, {%0,%1,%2,%3};"                \
        : "+f"(C0), "+f"(C1), "+f"(C2), "+f"(C3)                               \
        : "r"(A0), "r"(A1), "r"(A2), "r"(A3), "r"(B0), "r"(B1))

__device__ __forceinline__ float to_tf32(float x) {
    float y;
    asm("cvt.rna.tf32.f32 %0, %1;" : "=f"(y) : "f"(x));
    return y;
}

__global__ __launch_bounds__(256) void cost_kernel(const float* __restrict__ s1,
                                                   const float* __restrict__ s2) {
    __shared__ float smem[9216];       // asmem[128][36] + bsmem[128][36]; reused as Ss(half)[128][131]
    float* asmem = smem;
    float* bsmem = smem + 4608;

    int b = blockIdx.z;
    int i0 = blockIdx.y * 128;
    int j0 = blockIdx.x * 128;
    int tid = threadIdx.x;
    int lane = tid & 31;
    int w = tid >> 5;
    int wm = w >> 2;
    int wn = w & 3;
    int g = lane >> 2;
    int tg = lane & 3;

    const float* A = s1 + ((size_t)b * 1024 + i0) * 128;
    const float* B = s2 + ((size_t)b * 1024 + j0) * 128;

    float c[4][4][4];
#pragma unroll
    for (int mt = 0; mt < 4; mt++)
#pragma unroll
        for (int nt = 0; nt < 4; nt++)
#pragma unroll
            for (int q = 0; q < 4; q++) c[mt][nt][q] = 0.0f;

    for (int kc0 = 0; kc0 < 128; kc0 += 32) {
        __syncthreads();
#pragma unroll
        for (int it = 0; it < 4; it++) {
            int u = tid + it * 256;
            int r = u >> 3;
            int c0 = (u & 7) * 4;
            float4 va = *(const float4*)&A[r * 128 + kc0 + c0];
            va.x = to_tf32(va.x); va.y = to_tf32(va.y);
            va.z = to_tf32(va.z); va.w = to_tf32(va.w);
            *(float4*)&asmem[r * 36 + c0] = va;
            float4 vb = *(const float4*)&B[r * 128 + kc0 + c0];
            vb.x = to_tf32(vb.x); vb.y = to_tf32(vb.y);
            vb.z = to_tf32(vb.z); vb.w = to_tf32(vb.w);
            *(float4*)&bsmem[r * 36 + c0] = vb;
        }
        __syncthreads();

#pragma unroll
        for (int ks = 0; ks < 4; ks++) {
            unsigned af[4][4], bf[4][2];
#pragma unroll
            for (int mt = 0; mt < 4; mt++) {
                int ar = wm * 64 + mt * 16;
                af[mt][0] = __float_as_uint(asmem[(ar + g) * 36 + ks * 8 + tg]);
                af[mt][1] = __float_as_uint(asmem[(ar + 8 + g) * 36 + ks * 8 + tg]);
                af[mt][2] = __float_as_uint(asmem[(ar + g) * 36 + ks * 8 + tg + 4]);
                af[mt][3] = __float_as_uint(asmem[(ar + 8 + g) * 36 + ks * 8 + tg + 4]);
            }
#pragma unroll
            for (int nt = 0; nt < 4; nt++) {
                int br = wn * 32 + nt * 8;
                bf[nt][0] = __float_as_uint(bsmem[(br + g) * 36 + ks * 8 + tg]);
                bf[nt][1] = __float_as_uint(bsmem[(br + g) * 36 + ks * 8 + tg + 4]);
            }
#pragma unroll
            for (int mt = 0; mt < 4; mt++)
#pragma unroll
                for (int nt = 0; nt < 4; nt++)
                    MMA_TF32(c[mt][nt][0], c[mt][nt][1], c[mt][nt][2], c[mt][nt][3],
                             af[mt][0], af[mt][1], af[mt][2], af[mt][3],
                             bf[nt][0], bf[nt][1]);
        }
    }
    __syncthreads();

    // Epilogue: fp16 distances into staging buffer Ss[128][131].
    __half* Ss = (__half*)smem;
#pragma unroll
    for (int mt = 0; mt < 4; mt++) {
        int r0 = wm * 64 + mt * 16 + g;
        float n1a = g_n1[b * 1024 + i0 + r0];
        float n1b = g_n1[b * 1024 + i0 + r0 + 8];
#pragma unroll
        for (int nt = 0; nt < 4; nt++) {
            int c0 = wn * 32 + nt * 8 + 2 * tg;
            float n2a = g_n2[b * 1024 + j0 + c0];
            float n2b = g_n2[b * 1024 + j0 + c0 + 1];
            float d00 = n1a + n2a - 2.0f * c[mt][nt][0];
            float d01 = n1a + n2b - 2.0f * c[mt][nt][1];
            float d10 = n1b + n2a - 2.0f * c[mt][nt][2];
            float d11 = n1b + n2b - 2.0f * c[mt][nt][3];
            Ss[r0 * 131 + c0]           = __float2half_rn(sqrtf(fmaxf(d00, 0.0f)));
            Ss[r0 * 131 + c0 + 1]       = __float2half_rn(sqrtf(fmaxf(d01, 0.0f)));
            Ss[(r0 + 8) * 131 + c0]     = __float2half_rn(sqrtf(fmaxf(d10, 0.0f)));
            Ss[(r0 + 8) * 131 + c0 + 1] = __float2half_rn(sqrtf(fmaxf(d11, 0.0f)));
        }
    }
    __syncthreads();

    // Skewed writeout: sigma = kc + ((r>>3)&31), kc = i0+j0+rloc+jloc.
    // sloc = rloc + jloc + lt in [0,285]; for fixed sloc, stores over rloc are
    // contiguous halves -> coalesced.
    {
        int rloc = tid & 127;
        int sh = tid >> 7;             // 0 or 1
        int lt = ((i0 + rloc) >> 3) & 31;
        int rterm = rloc + lt;
        for (int sl = 0; sl < 286; sl += 2) {
            int sloc = sl + sh;
            int jloc = sloc - rterm;
            if (jloc >= 0 && jloc < 128) {
                size_t addr = ((size_t)b * SIG + (size_t)(i0 + j0 + sloc)) * 1024
                              + (size_t)(i0 + rloc);
                g_CH[addr] = Ss[rloc * 131 + jloc];
            }
        }
    }
}

// ---------------------------------------------------------------------------
// Kernel 2: DTW wavefront, 128 threads (1 warp/SMSP), 8 rows per thread,
// lane-skewed pipeline. Thread t owns DP rows 8t+1..8t+8 as register chains.
// Lane l runs 1 diagonal behind lane l-1: at (interval mb, step u) it processes
// diag k = 2 + mb*16 + u - l, reading lane-independent slot sigma = mb*16 + u
// (one coalesced LDG.128 of 8 fp16 per thread). The shfl_up of nm7 is issued
// at step tau, consumed at tau+1 (off the critical path). Warp w lags warp w-1
// by 4 intervals; boundary values flow through 4-buffered edge[4][4][16]:
// consumer at interval m reads slots from intervals m-2 (u>=1) and m-3 (u==0),
// hoisted to registers at interval start. Out-of-band cost slots are 0.0h ->
// maskless BIGF-propagation (same induction as R5-R7). Thread 127 captures
// D[1024][1024] at mb=129, u=13 (k==2048).
// ---------------------------------------------------------------------------
__global__ __launch_bounds__(128, 1) void dtw_kernel(float* __restrict__ out) {
    int b = blockIdx.x;
    int t = threadIdx.x;
    int lane = t & 31;
    int w = t >> 5;  // 4 warps

    __shared__ float edge[4][4][16];
    for (int s = t; s < 4 * 4 * 16; s += 128) (&edge[0][0][0])[s] = BIGF;
    __syncthreads();

    const uint4* C4 = (const uint4*)(g_CH + (size_t)b * SIG * 1024);
    // slot sigma, thread t -> C4[sigma*128 + t] = 8 fp16 costs, rows 8t..8t+7,
    // kc = sigma - lane.

    float prev[8], prev2[8];
#pragma unroll
    for (int r = 0; r < 8; r++) { prev[r] = BIGF; prev2[r] = BIGF; }

    uint4 cb[16];
#pragma unroll
    for (int q = 0; q < 16; q++) cb[q] = __ldcs(&C4[q * 128 + t]);

    float eup[16];
    float nextup = BIGF;
    float ans = BIGF;

    for (int m = 0; m < 142; ++m) {
        int mb = m - 4 * w;
        if (mb >= 0 && mb < 130) {
            // Hoist inter-warp boundary values for this interval.
            if (lane == 0) {
                if (w == 0) {
#pragma unroll
                    for (int u = 0; u < 16; u++) eup[u] = BIGF;
                    if (m == 0) eup[0] = 0.0f;      // D[0][0]=0 feeds k==2 only
                } else {
                    eup[0] = edge[(m + 1) & 3][w][15];       // produced at m-3
#pragma unroll
                    for (int u = 1; u < 16; u++)
                        eup[u] = edge[(m + 2) & 3][w][u - 1];  // produced at m-2
                }
            }
            const uint4* Cb = C4 + (size_t)(mb * 16) * 128 + t;
#pragma unroll
            for (int u = 0; u < 16; ++u) {
                uint4 cw = cb[u];
                cb[u] = __ldcs(Cb + (size_t)(u + 16) * 128);  // sigma+16 <= 2095 < SIG

                float2 f0 = __half22float2(*reinterpret_cast<__half2*>(&cw.x));
                float2 f1 = __half22float2(*reinterpret_cast<__half2*>(&cw.y));
                float2 f2 = __half22float2(*reinterpret_cast<__half2*>(&cw.z));
                float2 f3 = __half22float2(*reinterpret_cast<__half2*>(&cw.w));

                float up = (lane == 0) ? eup[u] : nextup;   // shfl result from prev step

                float nm0 = fminf(prev[0], prev2[0]);
                float nm1 = fminf(prev[1], prev2[1]);
                float nm2 = fminf(prev[2], prev2[2]);
                float nm3 = fminf(prev[3], prev2[3]);
                float nm4 = fminf(prev[4], prev2[4]);
                float nm5 = fminf(prev[5], prev2[5]);
                float nm6 = fminf(prev[6], prev2[6]);
                float nm7 = fminf(prev[7], prev2[7]);

                nextup = __shfl_up_sync(0xffffffffu, nm7, 1);   // consumed next step
                if (lane == 31 && w < 3) edge[m & 3][w + 1][u] = nm7;

                float c0 = f0.x + fminf(prev[0], up);
                float c1 = f0.y + fminf(prev[1], nm0);
                float c2 = f1.x + fminf(prev[2], nm1);
                float c3 = f1.y + fminf(prev[3], nm2);
                float c4 = f2.x + fminf(prev[4], nm3);
                float c5 = f2.y + fminf(prev[5], nm4);
                float c6 = f3.x + fminf(prev[6], nm5);
                float c7 = f3.y + fminf(prev[7], nm6);

                if (mb == 129 && u == 13) ans = c7;   // thread 127: D[1024][1024]

                prev2[0] = prev[0]; prev[0] = c0;
                prev2[1] = prev[1]; prev[1] = c1;
                prev2[2] = prev[2]; prev[2] = c2;
                prev2[3] = prev[3]; prev[3] = c3;
                prev2[4] = prev[4]; prev[4] = c4;
                prev2[5] = prev[5]; prev[5] = c5;
                prev2[6] = prev[6]; prev[6] = c6;
                prev2[7] = prev[7]; prev[7] = c7;
            }
        }
        __syncthreads();
    }

    if (t == 127) {
        // softmax over a single weight == 1 exactly.
        float dist = ans * (1.0f / 2048.0f);
        out[b] = 1.0f / (1.0f + dist);
    }
}

// ---------------------------------------------------------------------------
extern "C" void kernel_launch(void* const* d_in, const int* in_sizes, int n_in,
                              void* d_out, int out_size) {
    const float* seq1 = (const float*)d_in[0];
    const float* seq2 = (const float*)d_in[1];
    // d_in[2] = scale_weights (1 elem): softmax of a single weight is exactly 1.0.
    float* out = (float*)d_out;

    dim3 gN(128, 32, 2);
    norms_kernel<<<gN, 256>>>(seq1, seq2);

    dim3 gC(8, 8, 32);
    cost_kernel<<<gC, 256>>>(seq1, seq2);

    dtw_kernel<<<32, 128>>>(out);
}

// round 10
// speedup vs baseline: 1.0564x; 1.0564x over previous
#include <cuda_runtime.h>
#include <cuda_fp16.h>
#include <math.h>

#define BIGF 1000000000.0f
#define SIG 2144

// Cost matrix, fp16, SKEWED anti-diagonal layout:
// slot(b, sigma, r) at halves-address ((b*SIG + sigma)*1024 + r) holds
// C[r][kc] with kc = sigma - ((r>>2)&31). Zero-initialized; slots never
// written stay 0.0h (dtw's maskless induction relies on this).
static __device__ __align__(256) __half g_CH[70254592];   // 32*2144*1024
static __device__ float g_n1[32 * 1024];
static __device__ float g_n2[32 * 1024];
// Per-(batch, band) completed-tile counters. band s = ti+tj in [0,14].
static __device__ int g_band_done[512];                   // [b*16 + s]

__device__ __forceinline__ int bandn(int s) { return 8 - (s < 7 ? 7 - s : s - 7); }

// ---------------------------------------------------------------------------
// Kernel I: zero the progress counters (runs before the fused kernel).
// ---------------------------------------------------------------------------
__global__ void init_kernel() {
    g_band_done[threadIdx.x] = 0;
}

// ---------------------------------------------------------------------------
// Kernel 0: row squared norms (fp32). One warp per row.
// ---------------------------------------------------------------------------
__global__ __launch_bounds__(256) void norms_kernel(const float* __restrict__ s1,
                                                    const float* __restrict__ s2) {
    int b = blockIdx.y;
    const float* s = blockIdx.z ? s2 : s1;
    float* o = blockIdx.z ? g_n2 : g_n1;
    int lane = threadIdx.x & 31;
    int wid = threadIdx.x >> 5;
    int r = blockIdx.x * 8 + wid;
    const float4* p = (const float4*)(s + ((size_t)b * 1024 + r) * 128);
    float4 v = p[lane];
    float acc = v.x * v.x + v.y * v.y + v.z * v.z + v.w * v.w;
#pragma unroll
    for (int off = 16; off; off >>= 1)
        acc += __shfl_xor_sync(0xffffffffu, acc, off);
    if (lane == 0) o[b * 1024 + r] = acc;
}

// ---------------------------------------------------------------------------
// FUSED kernel: 2080 CTAs. CTAs 0..31 = DTW consumers (one per batch),
// scheduled first so they are resident from wave 1. CTAs 32..2079 = cost
// producer tiles, band-major (all tiles of band s = ti+tj before band s+1).
// Producers release-publish per-(batch,band) counters; consumers acquire-gate
// each 32-diagonal interval on prefix-complete bands.
// ---------------------------------------------------------------------------
#define MMA_TF32(C0, C1, C2, C3, A0, A1, A2, A3, B0, B1)                      \
    asm volatile(                                                              \
        "mma.sync.aligned.m16n8k8.row.col.f32.tf32.tf32.f32 "                  \
        "{%0,%1,%2,%3}, {%4,%5,%6,%7}, {%8,%9}, {%0,%1,%2,%3};"                \
        : "+f"(C0), "+f"(C1), "+f"(C2), "+f"(C3)                               \
        : "r"(A0), "r"(A1), "r"(A2), "r"(A3), "r"(B0), "r"(B1))

__device__ __forceinline__ float to_tf32(float x) {
    float y;
    asm("cvt.rna.tf32.f32 %0, %1;" : "=f"(y) : "f"(x));
    return y;
}

__global__ __launch_bounds__(256) void fused_kernel(const float* __restrict__ s1,
                                                    const float* __restrict__ s2,
                                                    float* __restrict__ out) {
    __shared__ float smem[9216];   // cost: asmem+bsmem / Ss staging; dtw: edge+flag

    if (blockIdx.x < 32) {
        // =================== DTW consumer role (R7 pipeline) ===================
        int b = blockIdx.x;
        int t = threadIdx.x;
        int lane = t & 31;
        int w = t >> 5;  // 8 warps

        float (*edge)[8][32] = (float (*)[8][32])smem;   // [3][8][32]
        int* sh_sok = (int*)(smem + 3 * 8 * 32);
        for (int s = t; s < 3 * 8 * 32; s += 256) (&edge[0][0][0])[s] = BIGF;

        // Gate: band 0 of this batch covers the initial prefetch (sigma 0..31).
        if (t == 0) {
            while (atomicAdd(&g_band_done[b * 16 + 0], 0) < 1) { }
            *sh_sok = 0;
            __threadfence();
        }
        __syncthreads();

        const uint2* C = (const uint2*)(g_CH + (size_t)b * SIG * 1024);

        float prev[4], prev2[4];
#pragma unroll
        for (int r = 0; r < 4; r++) { prev[r] = BIGF; prev2[r] = BIGF; }

        uint2 cb[32];
#pragma unroll
        for (int q = 0; q < 32; q++) cb[q] = __ldcs(&C[q * 256 + t]);

        float eup[32];
        float nextup = BIGF;
        float ans = BIGF;

        for (int m = 0; m < 79; ++m) {
            // Acquire-gate this interval's prefetch range (max sigma = m*32+63).
            {
                int need = (m * 32 + 63) >> 7;
                if (need > 14) need = 14;
                if (t == 0) {
                    int sok = *sh_sok;
                    while (sok < need) {
                        if (atomicAdd(&g_band_done[b * 16 + sok + 1], 0) >= bandn(sok + 1))
                            sok++;
                    }
                    *sh_sok = sok;
                    __threadfence();
                }
                __syncthreads();
            }

            int mb = m - 2 * w;
            if (mb >= 0 && mb <= 64) {
                if (lane == 0) {
                    if (w == 0) {
#pragma unroll
                        for (int u = 0; u < 32; u++) eup[u] = BIGF;
                        if (m == 0) eup[0] = 0.0f;      // D[0][0]=0 feeds k==2 only
                    } else {
                        eup[0] = edge[(m + 1) % 3][w][31];         // produced at m-2
#pragma unroll
                        for (int u = 1; u < 32; u++)
                            eup[u] = edge[(m + 2) % 3][w][u - 1];  // produced at m-1
                    }
                }
                int kb = 2 + mb * 32 - lane;                 // k = kb + u
                const uint2* Cbase = C + (size_t)(mb * 32) * 256 + t;
#pragma unroll
                for (int u = 0; u < 32; ++u) {
                    uint2 cw = cb[u];
                    cb[u] = __ldcs(Cbase + (size_t)(u + 32) * 256);  // sigma+32 <= 2111 < SIG

                    float2 f01 = __half22float2(*reinterpret_cast<__half2*>(&cw.x));
                    float2 f23 = __half22float2(*reinterpret_cast<__half2*>(&cw.y));

                    float up = (lane == 0) ? eup[u] : nextup;

                    float nm0 = fminf(prev[0], prev2[0]);
                    float nm1 = fminf(prev[1], prev2[1]);
                    float nm2 = fminf(prev[2], prev2[2]);
                    float nm3 = fminf(prev[3], prev2[3]);

                    nextup = __shfl_up_sync(0xffffffffu, nm3, 1);
                    if (lane == 31 && w < 7) edge[m % 3][w + 1][u] = nm3;

                    float c0 = f01.x + fminf(prev[0], up);
                    float c1 = f01.y + fminf(prev[1], nm0);
                    float c2 = f23.x + fminf(prev[2], nm1);
                    float c3 = f23.y + fminf(prev[3], nm2);

                    if (kb + u == 2048) ans = c3;   // thread 255: D[1024][1024]

                    prev2[0] = prev[0]; prev[0] = c0;
                    prev2[1] = prev[1]; prev[1] = c1;
                    prev2[2] = prev[2]; prev[2] = c2;
                    prev2[3] = prev[3]; prev[3] = c3;
                }
            }
            __syncthreads();
        }

        if (t == 255) {
            // softmax over a single weight == 1 exactly.
            float dist = ans * (1.0f / 2048.0f);
            out[b] = 1.0f / (1.0f + dist);
        }
        return;
    }

    // ===================== Cost producer role (R6/R7 math) =====================
    float* asmem = smem;
    float* bsmem = smem + 4608;

    // Band-major decode of (blockIdx.x - 32).
    int rem = blockIdx.x - 32;
    int s = 0;
    for (;;) {
        int sz = bandn(s) * 32;
        if (rem < sz) break;
        rem -= sz;
        s++;
    }
    int n = bandn(s);
    int b = rem / n;
    int idx = rem - b * n;
    int ti = (s > 7 ? s - 7 : 0) + idx;
    int tj = s - ti;
    int i0 = ti * 128;
    int j0 = tj * 128;

    int tid = threadIdx.x;
    int lane = tid & 31;
    int w = tid >> 5;
    int wm = w >> 2;
    int wn = w & 3;
    int g = lane >> 2;
    int tg = lane & 3;

    const float* A = s1 + ((size_t)b * 1024 + i0) * 128;
    const float* B = s2 + ((size_t)b * 1024 + j0) * 128;

    float c[4][4][4];
#pragma unroll
    for (int mt = 0; mt < 4; mt++)
#pragma unroll
        for (int nt = 0; nt < 4; nt++)
#pragma unroll
            for (int q = 0; q < 4; q++) c[mt][nt][q] = 0.0f;

    for (int kc0 = 0; kc0 < 128; kc0 += 32) {
        __syncthreads();
#pragma unroll
        for (int it = 0; it < 4; it++) {
            int u = tid + it * 256;
            int r = u >> 3;
            int c0 = (u & 7) * 4;
            float4 va = *(const float4*)&A[r * 128 + kc0 + c0];
            va.x = to_tf32(va.x); va.y = to_tf32(va.y);
            va.z = to_tf32(va.z); va.w = to_tf32(va.w);
            *(float4*)&asmem[r * 36 + c0] = va;
            float4 vb = *(const float4*)&B[r * 128 + kc0 + c0];
            vb.x = to_tf32(vb.x); vb.y = to_tf32(vb.y);
            vb.z = to_tf32(vb.z); vb.w = to_tf32(vb.w);
            *(float4*)&bsmem[r * 36 + c0] = vb;
        }
        __syncthreads();

#pragma unroll
        for (int ks = 0; ks < 4; ks++) {
            unsigned af[4][4], bf[4][2];
#pragma unroll
            for (int mt = 0; mt < 4; mt++) {
                int ar = wm * 64 + mt * 16;
                af[mt][0] = __float_as_uint(asmem[(ar + g) * 36 + ks * 8 + tg]);
                af[mt][1] = __float_as_uint(asmem[(ar + 8 + g) * 36 + ks * 8 + tg]);
                af[mt][2] = __float_as_uint(asmem[(ar + g) * 36 + ks * 8 + tg + 4]);
                af[mt][3] = __float_as_uint(asmem[(ar + 8 + g) * 36 + ks * 8 + tg + 4]);
            }
#pragma unroll
            for (int nt = 0; nt < 4; nt++) {
                int br = wn * 32 + nt * 8;
                bf[nt][0] = __float_as_uint(bsmem[(br + g) * 36 + ks * 8 + tg]);
                bf[nt][1] = __float_as_uint(bsmem[(br + g) * 36 + ks * 8 + tg + 4]);
            }
#pragma unroll
            for (int mt = 0; mt < 4; mt++)
#pragma unroll
                for (int nt = 0; nt < 4; nt++)
                    MMA_TF32(c[mt][nt][0], c[mt][nt][1], c[mt][nt][2], c[mt][nt][3],
                             af[mt][0], af[mt][1], af[mt][2], af[mt][3],
                             bf[nt][0], bf[nt][1]);
        }
    }
    __syncthreads();

    // Epilogue: fp16 distances into staging buffer Ss[128][131].
    __half* Ss = (__half*)smem;
#pragma unroll
    for (int mt = 0; mt < 4; mt++) {
        int r0 = wm * 64 + mt * 16 + g;
        float n1a = g_n1[b * 1024 + i0 + r0];
        float n1b = g_n1[b * 1024 + i0 + r0 + 8];
#pragma unroll
        for (int nt = 0; nt < 4; nt++) {
            int c0 = wn * 32 + nt * 8 + 2 * tg;
            float n2a = g_n2[b * 1024 + j0 + c0];
            float n2b = g_n2[b * 1024 + j0 + c0 + 1];
            float d00 = n1a + n2a - 2.0f * c[mt][nt][0];
            float d01 = n1a + n2b - 2.0f * c[mt][nt][1];
            float d10 = n1b + n2a - 2.0f * c[mt][nt][2];
            float d11 = n1b + n2b - 2.0f * c[mt][nt][3];
            Ss[r0 * 131 + c0]           = __float2half_rn(sqrtf(fmaxf(d00, 0.0f)));
            Ss[r0 * 131 + c0 + 1]       = __float2half_rn(sqrtf(fmaxf(d01, 0.0f)));
            Ss[(r0 + 8) * 131 + c0]     = __float2half_rn(sqrtf(fmaxf(d10, 0.0f)));
            Ss[(r0 + 8) * 131 + c0 + 1] = __float2half_rn(sqrtf(fmaxf(d11, 0.0f)));
        }
    }
    __syncthreads();

    // Skewed writeout: sigma_loc = rloc + jloc + ((i0+rloc)>>2 & 31) in [0,285].
    {
        int rloc = tid & 127;
        int sh = tid >> 7;
        int rterm = rloc + (((i0 + rloc) >> 2) & 31);
        for (int sl = 0; sl < 286; sl += 2) {
            int sloc = sl + sh;
            int jloc = sloc - rterm;
            if (jloc >= 0 && jloc < 128) {
                size_t addr = ((size_t)b * SIG + (size_t)(i0 + j0 + sloc)) * 1024
                              + (size_t)(i0 + rloc);
                g_CH[addr] = Ss[rloc * 131 + jloc];
            }
        }
    }

    // Release-publish tile completion.
    __syncthreads();
    if (tid == 0) {
        __threadfence();
        atomicAdd(&g_band_done[b * 16 + s], 1);
    }
}

// ---------------------------------------------------------------------------
extern "C" void kernel_launch(void* const* d_in, const int* in_sizes, int n_in,
                              void* d_out, int out_size) {
    const float* seq1 = (const float*)d_in[0];
    const float* seq2 = (const float*)d_in[1];
    // d_in[2] = scale_weights (1 elem): softmax of a single weight is exactly 1.0.
    float* out = (float*)d_out;

    init_kernel<<<1, 512>>>();

    dim3 gN(128, 32, 2);
    norms_kernel<<<gN, 256>>>(seq1, seq2);

    fused_kernel<<<2080, 256>>>(seq1, seq2, out);
}

// round 11
// speedup vs baseline: 1.1890x; 1.1256x over previous
#include <cuda_runtime.h>
#include <cuda_fp16.h>
#include <math.h>

#define BIGF 1000000000.0f
#define SIG 2144

// Cost matrix, fp16, SKEWED anti-diagonal layout:
// slot(b, sigma, r) at halves-address ((b*SIG + sigma)*1024 + r) holds
// C[r][kc] with kc = sigma - ((r>>2)&31). Zero-initialized; slots never
// written stay 0.0h (dtw's maskless induction relies on this).
static __device__ __align__(256) __half g_CH[70254592];   // 32*2144*1024
static __device__ float g_n1[32 * 1024];
static __device__ float g_n2[32 * 1024];

// ---------------------------------------------------------------------------
// Kernel 0: row squared norms (fp32). One warp per row.
// ---------------------------------------------------------------------------
__global__ __launch_bounds__(256) void norms_kernel(const float* __restrict__ s1,
                                                    const float* __restrict__ s2) {
    int b = blockIdx.y;
    const float* s = blockIdx.z ? s2 : s1;
    float* o = blockIdx.z ? g_n2 : g_n1;
    int lane = threadIdx.x & 31;
    int wid = threadIdx.x >> 5;
    int r = blockIdx.x * 8 + wid;
    const float4* p = (const float4*)(s + ((size_t)b * 1024 + r) * 128);
    float4 v = p[lane];
    float acc = v.x * v.x + v.y * v.y + v.z * v.z + v.w * v.w;
#pragma unroll
    for (int off = 16; off; off >>= 1)
        acc += __shfl_xor_sync(0xffffffffu, acc, off);
    if (lane == 0) o[b * 1024 + r] = acc;
}

// ---------------------------------------------------------------------------
// Kernel 1: cost matrix via tf32 mma.sync.m16n8k8.
// grid (8, 8, 32); CTA tile 128(i) x 128(j); 8 warps 2x4; warp tile 64x32.
// Fragment loads use the K-PAIR PERMUTATION: thread (g,tg)'s two k-slots are
// remapped from {tg, tg+4} to {2tg, 2tg+1} consistently for A and B. Since k
// is a contraction index and the remap is a bijection of 0..7, the result is
// bit-identical while every fragment load becomes one aligned LDS.64 (float2):
// 12 LDS.64 per warp-kstep instead of 24 LDS.32.
// Epilogue sqrt(max(n1+n2-2dot,0)) -> fp16 staged in shared (stride 131),
// written out in the skewed sigma-layout (coalesced per-sigma runs).
// ---------------------------------------------------------------------------
#define MMA_TF32(C0, C1, C2, C3, A0, A1, A2, A3, B0, B1)                      \
    asm volatile(                                                              \
        "mma.sync.aligned.m16n8k8.row.col.f32.tf32.tf32.f32 "                  \
        "{%0,%1,%2,%3}, {%4,%5,%6,%7}, {%8,%9}, {%0,%1,%2,%3};"                \
        : "+f"(C0), "+f"(C1), "+f"(C2), "+f"(C3)                               \
        : "r"(A0), "r"(A1), "r"(A2), "r"(A3), "r"(B0), "r"(B1))

__device__ __forceinline__ float to_tf32(float x) {
    float y;
    asm("cvt.rna.tf32.f32 %0, %1;" : "=f"(y) : "f"(x));
    return y;
}

__global__ __launch_bounds__(256) void cost_kernel(const float* __restrict__ s1,
                                                   const float* __restrict__ s2) {
    __shared__ float smem[9216];       // asmem[128][36] + bsmem[128][36]; reused as Ss(half)[128][131]
    float* asmem = smem;
    float* bsmem = smem + 4608;

    int b = blockIdx.z;
    int i0 = blockIdx.y * 128;
    int j0 = blockIdx.x * 128;
    int tid = threadIdx.x;
    int lane = tid & 31;
    int w = tid >> 5;
    int wm = w >> 2;
    int wn = w & 3;
    int g = lane >> 2;
    int tg = lane & 3;

    const float* A = s1 + ((size_t)b * 1024 + i0) * 128;
    const float* B = s2 + ((size_t)b * 1024 + j0) * 128;

    float c[4][4][4];
#pragma unroll
    for (int mt = 0; mt < 4; mt++)
#pragma unroll
        for (int nt = 0; nt < 4; nt++)
#pragma unroll
            for (int q = 0; q < 4; q++) c[mt][nt][q] = 0.0f;

    for (int kc0 = 0; kc0 < 128; kc0 += 32) {
        __syncthreads();
#pragma unroll
        for (int it = 0; it < 4; it++) {
            int u = tid + it * 256;
            int r = u >> 3;
            int c0 = (u & 7) * 4;
            float4 va = *(const float4*)&A[r * 128 + kc0 + c0];
            va.x = to_tf32(va.x); va.y = to_tf32(va.y);
            va.z = to_tf32(va.z); va.w = to_tf32(va.w);
            *(float4*)&asmem[r * 36 + c0] = va;
            float4 vb = *(const float4*)&B[r * 128 + kc0 + c0];
            vb.x = to_tf32(vb.x); vb.y = to_tf32(vb.y);
            vb.z = to_tf32(vb.z); vb.w = to_tf32(vb.w);
            *(float4*)&bsmem[r * 36 + c0] = vb;
        }
        __syncthreads();

#pragma unroll
        for (int ks = 0; ks < 4; ks++) {
            unsigned af[4][4], bf[4][2];
#pragma unroll
            for (int mt = 0; mt < 4; mt++) {
                int ar = wm * 64 + mt * 16;
                float2 alo = *(const float2*)&asmem[(ar + g) * 36 + ks * 8 + 2 * tg];
                float2 ahi = *(const float2*)&asmem[(ar + 8 + g) * 36 + ks * 8 + 2 * tg];
                af[mt][0] = __float_as_uint(alo.x);   // k = 2tg
                af[mt][1] = __float_as_uint(ahi.x);
                af[mt][2] = __float_as_uint(alo.y);   // k = 2tg+1
                af[mt][3] = __float_as_uint(ahi.y);
            }
#pragma unroll
            for (int nt = 0; nt < 4; nt++) {
                int br = wn * 32 + nt * 8;
                float2 bp = *(const float2*)&bsmem[(br + g) * 36 + ks * 8 + 2 * tg];
                bf[nt][0] = __float_as_uint(bp.x);    // k = 2tg
                bf[nt][1] = __float_as_uint(bp.y);    // k = 2tg+1
            }
#pragma unroll
            for (int mt = 0; mt < 4; mt++)
#pragma unroll
                for (int nt = 0; nt < 4; nt++)
                    MMA_TF32(c[mt][nt][0], c[mt][nt][1], c[mt][nt][2], c[mt][nt][3],
                             af[mt][0], af[mt][1], af[mt][2], af[mt][3],
                             bf[nt][0], bf[nt][1]);
        }
    }
    __syncthreads();

    // Epilogue: fp16 distances into staging buffer Ss[128][131].
    __half* Ss = (__half*)smem;
#pragma unroll
    for (int mt = 0; mt < 4; mt++) {
        int r0 = wm * 64 + mt * 16 + g;
        float n1a = g_n1[b * 1024 + i0 + r0];
        float n1b = g_n1[b * 1024 + i0 + r0 + 8];
#pragma unroll
        for (int nt = 0; nt < 4; nt++) {
            int c0 = wn * 32 + nt * 8 + 2 * tg;
            float n2a = g_n2[b * 1024 + j0 + c0];
            float n2b = g_n2[b * 1024 + j0 + c0 + 1];
            float d00 = n1a + n2a - 2.0f * c[mt][nt][0];
            float d01 = n1a + n2b - 2.0f * c[mt][nt][1];
            float d10 = n1b + n2a - 2.0f * c[mt][nt][2];
            float d11 = n1b + n2b - 2.0f * c[mt][nt][3];
            Ss[r0 * 131 + c0]           = __float2half_rn(sqrtf(fmaxf(d00, 0.0f)));
            Ss[r0 * 131 + c0 + 1]       = __float2half_rn(sqrtf(fmaxf(d01, 0.0f)));
            Ss[(r0 + 8) * 131 + c0]     = __float2half_rn(sqrtf(fmaxf(d10, 0.0f)));
            Ss[(r0 + 8) * 131 + c0 + 1] = __float2half_rn(sqrtf(fmaxf(d11, 0.0f)));
        }
    }
    __syncthreads();

    // Skewed writeout: sigma_loc = rloc + jloc + ((i0+rloc)>>2 & 31) in [0,285].
    {
        int rloc = tid & 127;
        int sh = tid >> 7;
        int rterm = rloc + (((i0 + rloc) >> 2) & 31);
        for (int sl = 0; sl < 286; sl += 2) {
            int sloc = sl + sh;
            int jloc = sloc - rterm;
            if (jloc >= 0 && jloc < 128) {
                size_t addr = ((size_t)b * SIG + (size_t)(i0 + j0 + sloc)) * 1024
                              + (size_t)(i0 + rloc);
                g_CH[addr] = Ss[rloc * 131 + jloc];
            }
        }
    }
}

// ---------------------------------------------------------------------------
// Kernel 2: DTW wavefront, lane-skewed pipeline (R7, unchanged). 256 threads,
// thread t owns DP rows 4t+1..4t+4 (register chain); lane l runs 1 diagonal
// behind lane l-1, reading lane-independent slot sigma = mb*32 + u (coalesced);
// the shfl_up is issued at step tau and consumed at tau+1 (off the critical
// path). Warp w lags warp w-1 by 2 intervals via triple-buffered edge[3][8][32]
// hoisted to registers at interval start. Out-of-band cost slots are 0.0h ->
// maskless BIGF-propagation. Thread 255 captures D[1024][1024] at k==2048.
// ---------------------------------------------------------------------------
__global__ __launch_bounds__(256, 1) void dtw_kernel(float* __restrict__ out) {
    int b = blockIdx.x;
    int t = threadIdx.x;
    int lane = t & 31;
    int w = t >> 5;  // 8 warps

    __shared__ float edge[3][8][32];
    for (int s = t; s < 3 * 8 * 32; s += 256) (&edge[0][0][0])[s] = BIGF;
    __syncthreads();

    const uint2* C = (const uint2*)(g_CH + (size_t)b * SIG * 1024);

    float prev[4], prev2[4];
#pragma unroll
    for (int r = 0; r < 4; r++) { prev[r] = BIGF; prev2[r] = BIGF; }

    uint2 cb[32];
#pragma unroll
    for (int q = 0; q < 32; q++) cb[q] = __ldcs(&C[q * 256 + t]);

    float eup[32];
    float nextup = BIGF;
    float ans = BIGF;

    for (int m = 0; m < 79; ++m) {
        int mb = m - 2 * w;
        if (mb >= 0 && mb <= 64) {
            if (lane == 0) {
                if (w == 0) {
#pragma unroll
                    for (int u = 0; u < 32; u++) eup[u] = BIGF;
                    if (m == 0) eup[0] = 0.0f;      // D[0][0]=0 feeds k==2 only
                } else {
                    eup[0] = edge[(m + 1) % 3][w][31];         // produced at m-2
#pragma unroll
                    for (int u = 1; u < 32; u++)
                        eup[u] = edge[(m + 2) % 3][w][u - 1];  // produced at m-1
                }
            }
            int kb = 2 + mb * 32 - lane;                 // k = kb + u
            const uint2* Cbase = C + (size_t)(mb * 32) * 256 + t;
#pragma unroll
            for (int u = 0; u < 32; ++u) {
                uint2 cw = cb[u];
                cb[u] = __ldcs(Cbase + (size_t)(u + 32) * 256);  // sigma+32 <= 2111 < SIG

                float2 f01 = __half22float2(*reinterpret_cast<__half2*>(&cw.x));
                float2 f23 = __half22float2(*reinterpret_cast<__half2*>(&cw.y));

                float up = (lane == 0) ? eup[u] : nextup;

                float nm0 = fminf(prev[0], prev2[0]);
                float nm1 = fminf(prev[1], prev2[1]);
                float nm2 = fminf(prev[2], prev2[2]);
                float nm3 = fminf(prev[3], prev2[3]);

                nextup = __shfl_up_sync(0xffffffffu, nm3, 1);
                if (lane == 31 && w < 7) edge[m % 3][w + 1][u] = nm3;

                float c0 = f01.x + fminf(prev[0], up);
                float c1 = f01.y + fminf(prev[1], nm0);
                float c2 = f23.x + fminf(prev[2], nm1);
                float c3 = f23.y + fminf(prev[3], nm2);

                if (kb + u == 2048) ans = c3;   // thread 255: D[1024][1024]

                prev2[0] = prev[0]; prev[0] = c0;
                prev2[1] = prev[1]; prev[1] = c1;
                prev2[2] = prev[2]; prev[2] = c2;
                prev2[3] = prev[3]; prev[3] = c3;
            }
        }
        __syncthreads();
    }

    if (t == 255) {
        // softmax over a single weight == 1 exactly.
        float dist = ans * (1.0f / 2048.0f);
        out[b] = 1.0f / (1.0f + dist);
    }
}

// ---------------------------------------------------------------------------
extern "C" void kernel_launch(void* const* d_in, const int* in_sizes, int n_in,
                              void* d_out, int out_size) {
    const float* seq1 = (const float*)d_in[0];
    const float* seq2 = (const float*)d_in[1];
    // d_in[2] = scale_weights (1 elem): softmax of a single weight is exactly 1.0.
    float* out = (float*)d_out;

    dim3 gN(128, 32, 2);
    norms_kernel<<<gN, 256>>>(seq1, seq2);

    dim3 gC(8, 8, 32);
    cost_kernel<<<gC, 256>>>(seq1, seq2);

    dtw_kernel<<<32, 256>>>(out);
}